// round 14
// baseline (speedup 1.0000x reference)
#include <cuda_runtime.h>
#include <math.h>

#define BB 2048
#define DD 512
#define CC 128
#define TT 151
#define G3 1536    // 3*D
#define ROWS 14    // batch rows per CTA (148 CTAs x 14 = 2072 >= 2048; tail padded)
#define NCTA 148   // one CTA per SM
#define PAIRS 7    // ROWS/2 f32x2 pairs
#define NT 512     // threads per CTA
#define HSTR 20    // h tile row stride in floats (80B: 16B-aligned, 4-way-conflict scalar access)

typedef unsigned long long ull;

// ---------------- device scratch (static globals; no allocation) ----------------
__device__ float  g_G[129 * G3];               // gi table: G[c] = embed[c]@W_ih^T + b_ih; row 128 = b_ih (zero start)
__device__ float4 g_W4[(DD / 4) * G3];         // W_hh transposed + k-packed: g_W4[kq*G3+j] = (Wt[4kq][j]..Wt[4kq+3][j])
__device__ float4 g_Wp4[(DD / 4) * CC];        // W_proj transposed + k-packed: g_Wp4[kq*CC+c] = (Wpt[4kq][c]..)
__device__ float  g_stage[(size_t)BB * TT * CC]; // logits staged [B][T][C], transposed at end

// ---------------- packed f32x2 helpers ----------------
__device__ __forceinline__ void fma2(ull& acc, ull a, ull b) {
    asm("fma.rn.f32x2 %0, %1, %2, %0;" : "+l"(acc) : "l"(a), "l"(b));
}
__device__ __forceinline__ ull pack2(float x, float y) {
    ull r; asm("mov.b64 %0, {%1,%2};" : "=l"(r) : "f"(x), "f"(y)); return r;
}
__device__ __forceinline__ float2 unpack2(ull v) {
    float2 r; asm("mov.b64 {%0,%1}, %2;" : "=f"(r.x), "=f"(r.y) : "l"(v)); return r;
}
// streaming (evict-first) stores/loads for write-once data (protect L2-resident weights)
__device__ __forceinline__ void st_cs4(float* p, float4 v) {
    asm volatile("st.global.cs.v4.f32 [%0], {%1,%2,%3,%4};"
                 :: "l"(p), "f"(v.x), "f"(v.y), "f"(v.z), "f"(v.w) : "memory");
}
__device__ __forceinline__ float ld_cs(const float* p) {
    float v; asm volatile("ld.global.cs.f32 %0, [%1];" : "=f"(v) : "l"(p)); return v;
}
__device__ __forceinline__ void st_cs(float* p, float v) {
    asm volatile("st.global.cs.f32 [%0], %1;" :: "l"(p), "f"(v) : "memory");
}
// constant-index float4 component (folds under full unroll)
__device__ __forceinline__ float f4c(float4 v, int kk) {
    return kk == 0 ? v.x : kk == 1 ? v.y : kk == 2 ? v.z : v.w;
}

// ---------------- precompute: G table ----------------
__global__ void precomp_G(const float* __restrict__ embed,
                          const float* __restrict__ W_ih,
                          const float* __restrict__ b_ih) {
    __shared__ float es[DD];
    int c = blockIdx.x;           // 0..128 (128 = zero start token)
    int tid = threadIdx.x;
    if (c < CC) {
        for (int i = tid; i < DD; i += 256) es[i] = embed[(size_t)c * DD + i];
    }
    __syncthreads();
    for (int j = tid; j < G3; j += 256) {
        float acc = b_ih[j];
        if (c < CC) {
            const float* w = W_ih + (size_t)j * DD;
            float s = 0.f;
            #pragma unroll 4
            for (int k = 0; k < DD; k += 4) {
                float4 w4 = *(const float4*)(w + k);
                s += w4.x * es[k] + w4.y * es[k + 1] + w4.z * es[k + 2] + w4.w * es[k + 3];
            }
            acc += s;
        }
        g_G[(size_t)c * G3 + j] = acc;
    }
}

// ---------------- precompute: W_hh -> transposed, k-packed float4 ----------------
__global__ void precomp_W4(const float* __restrict__ W_hh) {
    int idx = blockIdx.x * 256 + threadIdx.x;     // over (DD/4)*G3 = 196608
    if (idx < (DD / 4) * G3) {
        int kq = idx / G3;
        int j  = idx - kq * G3;
        int k0 = kq * 4;
        const float* wr = W_hh + (size_t)j * DD + k0;   // Wt[k][j] = W_hh[j*DD+k]
        g_W4[idx] = make_float4(wr[0], wr[1], wr[2], wr[3]);
    }
}

// ---------------- precompute: W_proj -> transposed, k-packed float4 ----------------
__global__ void precomp_Wp4(const float* __restrict__ W_proj) {
    int idx = blockIdx.x * 256 + threadIdx.x;     // over (DD/4)*CC = 16384
    if (idx < (DD / 4) * CC) {
        int kq = idx >> 7;
        int c  = idx & 127;
        const float* wr = W_proj + (size_t)c * DD + kq * 4;  // Wpt[k][c] = W_proj[c*DD+k]
        g_Wp4[idx] = make_float4(wr[0], wr[1], wr[2], wr[3]);
    }
}

// ---------------- persistent fused GRU decode ----------------
// One CTA per SM owns 14 batch rows for the ENTIRE sequence (rows independent).
// smem: hA[512][20] + hB[512][20] (transposed h ping-pong, rows 14..19 = pad) + lg[16][128].
__global__ __launch_bounds__(NT) void gru_kernel(
    const float* __restrict__ feat,
    const float* __restrict__ b_hh,
    const float* __restrict__ b_proj,
    float* __restrict__ out_tok)     // d_out + B*C*T (float tokens), or null
{
    extern __shared__ float sm[];
    float* hA = sm;                   // [k][HSTR]
    float* hB = sm + DD * HSTR;
    float* lg = sm + 2 * DD * HSTR;   // [16][128] (rows 14,15 scratch)
    __shared__ int tok_s[ROWS];

    const int tid = threadIdx.x;
    const int rb  = blockIdx.x * ROWS;

    // ---- load feat tile transposed into hA (h0 = feat); fake rows (>=BB) -> 0 ----
    #pragma unroll
    for (int i = 0; i < 4; i++) {
        int idx = tid + i * NT;       // need 14*128 = 1792 float4
        if (idx < ROWS * 128) {
            int b  = idx >> 7;
            int kq = idx & 127;
            float4 v = make_float4(0.f, 0.f, 0.f, 0.f);
            if (rb + b < BB)
                v = *(const float4*)(feat + (size_t)(rb + b) * DD + kq * 4);
            int base = (kq * 4) * HSTR + b;
            hA[base]            = v.x;
            hA[base + HSTR]     = v.y;
            hA[base + 2 * HSTR] = v.z;
            hA[base + 3 * HSTR] = v.w;
        }
    }
    if (tid < ROWS) tok_s[tid] = CC;  // x0 = 0 -> G row 128 (= b_ih only)
    __syncthreads();

    // per-thread invariants
    const int d = tid;                              // gh: owns gate dim d
    const float bhr = __ldg(&b_hh[d]);
    const float bhz = __ldg(&b_hh[DD + d]);
    const float bhn = __ldg(&b_hh[2 * DD + d]);
    const int   lc   = tid & 127;                   // logits: owns column lc
    const int   lb0  = (tid >> 7) * 4;              // ... for rows lb0..lb0+3 (group 3 partly scratch)
    const float bpc  = __ldg(&b_proj[lc]);

    for (int t = 0; t < TT; t++) {
        float* cur = (t & 1) ? hB : hA;
        float* nxt = (t & 1) ? hA : hB;

        // ---- gh GEMM: acc[j][b] = sum_k Wt[k][j] * h[k][b] ----
        // float4 weight k-packs, double-buffered at kq granularity (prefetch 1 kq
        // ahead = ~670-cycle cover > L2 262). h rows via 3xLDS.128 + 1xLDS.64.
        ull ar[PAIRS], az[PAIRS], an[PAIRS];
        #pragma unroll
        for (int p = 0; p < PAIRS; p++) { ar[p] = 0ULL; az[p] = 0ULL; an[p] = 0ULL; }

        float4 wbuf[2][3];
        const float4* wbase = g_W4 + d;
        wbuf[0][0] = __ldg(wbase);
        wbuf[0][1] = __ldg(wbase + DD);
        wbuf[0][2] = __ldg(wbase + 2 * DD);
        const float* hrow = cur;
        #pragma unroll 4
        for (int kq = 0; kq < 128; kq++) {
            const int cb = kq & 1, nb = cb ^ 1;
            if (kq < 127) {                    // prefetch next kq block
                const float4* w = wbase + (size_t)(kq + 1) * G3;
                wbuf[nb][0] = __ldg(w);
                wbuf[nb][1] = __ldg(w + DD);
                wbuf[nb][2] = __ldg(w + 2 * DD);
            }
            #pragma unroll
            for (int kk = 0; kk < 4; kk++) {
                // h row (k = 4kq+kk): rows 0..13 as 7 f32x2 pairs
                ulonglong2 hu0 = *(const ulonglong2*)(hrow);       // rows 0-3
                ulonglong2 hu1 = *(const ulonglong2*)(hrow + 4);   // rows 4-7
                ulonglong2 hu2 = *(const ulonglong2*)(hrow + 8);   // rows 8-11
                ull        hu3 = *(const ull*)(hrow + 12);         // rows 12-13
                hrow += HSTR;
                float wr = f4c(wbuf[cb][0], kk);
                float wz = f4c(wbuf[cb][1], kk);
                float wn = f4c(wbuf[cb][2], kk);
                ull wr2 = pack2(wr, wr);
                ull wz2 = pack2(wz, wz);
                ull wn2 = pack2(wn, wn);
                fma2(ar[0], wr2, hu0.x); fma2(az[0], wz2, hu0.x); fma2(an[0], wn2, hu0.x);
                fma2(ar[1], wr2, hu0.y); fma2(az[1], wz2, hu0.y); fma2(an[1], wn2, hu0.y);
                fma2(ar[2], wr2, hu1.x); fma2(az[2], wz2, hu1.x); fma2(an[2], wn2, hu1.x);
                fma2(ar[3], wr2, hu1.y); fma2(az[3], wz2, hu1.y); fma2(an[3], wn2, hu1.y);
                fma2(ar[4], wr2, hu2.x); fma2(az[4], wz2, hu2.x); fma2(an[4], wn2, hu2.x);
                fma2(ar[5], wr2, hu2.y); fma2(az[5], wz2, hu2.y); fma2(an[5], wn2, hu2.y);
                fma2(ar[6], wr2, hu3);   fma2(az[6], wz2, hu3);   fma2(an[6], wn2, hu3);
            }
        }

        // ---- gates + h_new (gi gathers batched so ptxas can front-issue them) ----
        #pragma unroll
        for (int p = 0; p < PAIRS; p++) {
            float2 rr = unpack2(ar[p]);
            float2 zz = unpack2(az[p]);
            float2 nn = unpack2(an[p]);
            const float* gi0 = g_G + (size_t)tok_s[2 * p] * G3;
            const float* gi1 = g_G + (size_t)tok_s[2 * p + 1] * G3;
            float gr0 = __ldg(&gi0[d]), gz0 = __ldg(&gi0[DD + d]), gn0 = __ldg(&gi0[2 * DD + d]);
            float gr1 = __ldg(&gi1[d]), gz1 = __ldg(&gi1[DD + d]), gn1 = __ldg(&gi1[2 * DD + d]);
            {
                int b = 2 * p;
                float r = 1.f / (1.f + expf(-(gr0 + rr.x + bhr)));
                float z = 1.f / (1.f + expf(-(gz0 + zz.x + bhz)));
                float n = tanhf(gn0 + r * (nn.x + bhn));
                float ho = cur[d * HSTR + b];
                nxt[d * HSTR + b] = (1.f - z) * n + z * ho;
            }
            {
                int b = 2 * p + 1;
                float r = 1.f / (1.f + expf(-(gr1 + rr.y + bhr)));
                float z = 1.f / (1.f + expf(-(gz1 + zz.y + bhz)));
                float n = tanhf(gn1 + r * (nn.y + bhn));
                float ho = cur[d * HSTR + b];
                nxt[d * HSTR + b] = (1.f - z) * n + z * ho;
            }
        }
        __syncthreads();   // h_new complete

        // ---- logits GEMM: thread = (col lc, rows lb0..lb0+3); 1 LDS.128/k + float4 weights ----
        // (group lb0=12: rows 14,15 are uninitialized pad -> garbage into lg scratch rows, never used)
        {
            ull a0 = 0ULL, a1 = 0ULL;
            const float4* wp4 = g_Wp4 + lc;
            const float* hr = nxt + lb0;
            #pragma unroll 4
            for (int kq = 0; kq < 128; kq++) {
                float4 w4 = __ldg(wp4); wp4 += CC;
                #pragma unroll
                for (int kk = 0; kk < 4; kk++) {
                    ulonglong2 H = *(const ulonglong2*)(hr);   // rows lb0..lb0+3
                    hr += HSTR;
                    float w = f4c(w4, kk);
                    ull w2 = pack2(w, w);
                    fma2(a0, w2, H.x);
                    fma2(a1, w2, H.y);
                }
            }
            float2 v0 = unpack2(a0);
            float2 v1 = unpack2(a1);
            lg[(lb0    ) * 128 + lc] = v0.x + bpc;
            lg[(lb0 + 1) * 128 + lc] = v0.y + bpc;
            lg[(lb0 + 2) * 128 + lc] = v1.x + bpc;
            lg[(lb0 + 3) * 128 + lc] = v1.y + bpc;
        }
        __syncthreads();   // logits complete

        // ---- stage logits [B][T][C] coalesced, streaming ----
        if (tid < ROWS * 32) {        // 448 float4 = 14*128
            int b  = tid >> 5;
            int cq = tid & 31;
            if (rb + b < BB) {
                float4 v = *(const float4*)(lg + b * 128 + cq * 4);
                st_cs4(g_stage + ((size_t)(rb + b) * TT + t) * CC + cq * 4, v);
            }
        }

        // ---- parallel argmax (first-max semantics) + token feedback ----
        if (tid < ROWS * 16) {        // 224 threads = 7 full warps
            int row = tid >> 4;
            int l16 = tid & 15;
            const float* lrow = lg + row * 128;
            float best = -3.4e38f;
            int bi = 0;
            #pragma unroll
            for (int j = 0; j < 8; j++) {
                int c = l16 + 16 * j;          // increasing c per thread
                float v = lrow[c];
                if (v > best) { best = v; bi = c; }
            }
            #pragma unroll
            for (int mask = 8; mask >= 1; mask >>= 1) {
                float ob  = __shfl_xor_sync(0xffffffffu, best, mask);
                int   obi = __shfl_xor_sync(0xffffffffu, bi,   mask);
                if (ob > best || (ob == best && obi < bi)) { best = ob; bi = obi; }
            }
            if (l16 == 0) {
                tok_s[row] = bi;               // always 0..127: g_G index stays in-bounds even for fake rows
                if (out_tok && rb + row < BB)
                    out_tok[(size_t)(rb + row) * TT + t] = (float)bi;
            }
        }
        __syncthreads();   // tok_s ready; lg & old cur free for reuse
    }
}

// ---------------- final transpose: stage[B][T][C] -> out[B][C][T] ----------------
__global__ void transpose_kernel(float* __restrict__ out) {
    __shared__ float tile[32][33];
    int b  = blockIdx.z;
    int t0 = blockIdx.x * 32;
    int c0 = blockIdx.y * 32;
    int tx = threadIdx.x, ty = threadIdx.y;   // block (32,8)
    #pragma unroll
    for (int i = 0; i < 4; i++) {
        int t = t0 + ty + i * 8;
        if (t < TT)
            tile[ty + i * 8][tx] = ld_cs(&g_stage[((size_t)b * TT + t) * CC + c0 + tx]);
    }
    __syncthreads();
    #pragma unroll
    for (int i = 0; i < 4; i++) {
        int c = c0 + ty + i * 8;
        int t = t0 + tx;
        if (t < TT)
            st_cs(&out[((size_t)b * CC + c) * TT + t], tile[tx][ty + i * 8]);
    }
}

// ---------------- launch ----------------
extern "C" void kernel_launch(void* const* d_in, const int* in_sizes, int n_in,
                              void* d_out, int out_size) {
    const float* feat   = (const float*)d_in[0];
    const float* W_ih   = (const float*)d_in[1];
    const float* W_hh   = (const float*)d_in[2];
    const float* b_ih   = (const float*)d_in[3];
    const float* b_hh   = (const float*)d_in[4];
    const float* W_proj = (const float*)d_in[5];
    const float* b_proj = (const float*)d_in[6];
    const float* embed  = (const float*)d_in[7];
    float* out = (float*)d_out;

    const int SMEM_BYTES = (2 * DD * HSTR + 16 * CC) * 4;   // 90112
    cudaFuncSetAttribute(gru_kernel, cudaFuncAttributeMaxDynamicSharedMemorySize, SMEM_BYTES);

    // precompute (cheap; replayed each graph iteration)
    precomp_G<<<129, 256>>>(embed, W_ih, b_ih);
    precomp_W4<<<((DD / 4) * G3 + 255) / 256, 256>>>(W_hh);
    precomp_Wp4<<<((DD / 4) * CC + 255) / 256, 256>>>(W_proj);

    const long long expected = (long long)BB * CC * TT + (long long)BB * TT;
    float* out_tok = ((long long)out_size >= expected) ? out + (size_t)BB * CC * TT : nullptr;

    // persistent kernel: whole T loop inside, one CTA per SM
    gru_kernel<<<NCTA, NT, SMEM_BYTES>>>(feat, b_hh, b_proj, out_tok);

    dim3 tb(32, 8);
    dim3 tg((TT + 31) / 32, CC / 32, BB);
    transpose_kernel<<<tg, tb>>>(out);
}

// round 17
// speedup vs baseline: 1.0183x; 1.0183x over previous
#include <cuda_runtime.h>
#include <math.h>

#define BB 2048
#define DD 512
#define CC 128
#define TT 151
#define G3 1536    // 3*D
#define ROWS 14    // batch rows per CTA (148 CTAs x 14 = 2072 >= 2048; tail padded)
#define NCTA 148   // one CTA per SM
#define PAIRS 7    // ROWS/2 f32x2 pairs
#define NT 512     // threads per CTA
#define HSTR 20    // h tile row stride in floats (80B: 16B-aligned)

typedef unsigned long long ull;

// ---------------- device scratch (static globals; no allocation) ----------------
__device__ float  g_G[129 * G3];               // gi table: G[c] = embed[c]@W_ih^T + b_ih; row 128 = b_ih (zero start)
__device__ float4 g_W4[(DD / 4) * G3];         // W_hh transposed + k-packed: g_W4[kq*G3+j] = (Wt[4kq][j]..Wt[4kq+3][j])
__device__ float4 g_Wp4[(DD / 4) * CC];        // W_proj transposed + k-packed: g_Wp4[kq*CC+c] = (Wpt[4kq][c]..)
__device__ float  g_stage[(size_t)BB * TT * CC]; // logits staged [B][T][C], transposed at end

// ---------------- packed f32x2 helpers ----------------
__device__ __forceinline__ void fma2(ull& acc, ull a, ull b) {
    asm("fma.rn.f32x2 %0, %1, %2, %0;" : "+l"(acc) : "l"(a), "l"(b));
}
__device__ __forceinline__ ull pack2(float x, float y) {
    ull r; asm("mov.b64 %0, {%1,%2};" : "=l"(r) : "f"(x), "f"(y)); return r;
}
__device__ __forceinline__ float2 unpack2(ull v) {
    float2 r; asm("mov.b64 {%0,%1}, %2;" : "=f"(r.x), "=f"(r.y) : "l"(v)); return r;
}
// streaming (evict-first) stores/loads for write-once data (protect L2-resident weights)
__device__ __forceinline__ void st_cs4(float* p, float4 v) {
    asm volatile("st.global.cs.v4.f32 [%0], {%1,%2,%3,%4};"
                 :: "l"(p), "f"(v.x), "f"(v.y), "f"(v.z), "f"(v.w) : "memory");
}
__device__ __forceinline__ float ld_cs(const float* p) {
    float v; asm volatile("ld.global.cs.f32 %0, [%1];" : "=f"(v) : "l"(p)); return v;
}
__device__ __forceinline__ void st_cs(float* p, float v) {
    asm volatile("st.global.cs.f32 [%0], %1;" :: "l"(p), "f"(v) : "memory");
}
// constant-index float4 component (folds under full unroll)
__device__ __forceinline__ float f4c(float4 v, int kk) {
    return kk == 0 ? v.x : kk == 1 ? v.y : kk == 2 ? v.z : v.w;
}

// ---------------- precompute: G table ----------------
__global__ void precomp_G(const float* __restrict__ embed,
                          const float* __restrict__ W_ih,
                          const float* __restrict__ b_ih) {
    __shared__ float es[DD];
    int c = blockIdx.x;           // 0..128 (128 = zero start token)
    int tid = threadIdx.x;
    if (c < CC) {
        for (int i = tid; i < DD; i += 256) es[i] = embed[(size_t)c * DD + i];
    }
    __syncthreads();
    for (int j = tid; j < G3; j += 256) {
        float acc = b_ih[j];
        if (c < CC) {
            const float* w = W_ih + (size_t)j * DD;
            float s = 0.f;
            #pragma unroll 4
            for (int k = 0; k < DD; k += 4) {
                float4 w4 = *(const float4*)(w + k);
                s += w4.x * es[k] + w4.y * es[k + 1] + w4.z * es[k + 2] + w4.w * es[k + 3];
            }
            acc += s;
        }
        g_G[(size_t)c * G3 + j] = acc;
    }
}

// ---------------- precompute: W_hh -> transposed, k-packed float4 ----------------
__global__ void precomp_W4(const float* __restrict__ W_hh) {
    int idx = blockIdx.x * 256 + threadIdx.x;     // over (DD/4)*G3 = 196608
    if (idx < (DD / 4) * G3) {
        int kq = idx / G3;
        int j  = idx - kq * G3;
        int k0 = kq * 4;
        const float* wr = W_hh + (size_t)j * DD + k0;   // Wt[k][j] = W_hh[j*DD+k]
        g_W4[idx] = make_float4(wr[0], wr[1], wr[2], wr[3]);
    }
}

// ---------------- precompute: W_proj -> transposed, k-packed float4 ----------------
__global__ void precomp_Wp4(const float* __restrict__ W_proj) {
    int idx = blockIdx.x * 256 + threadIdx.x;     // over (DD/4)*CC = 16384
    if (idx < (DD / 4) * CC) {
        int kq = idx >> 7;
        int c  = idx & 127;
        const float* wr = W_proj + (size_t)c * DD + kq * 4;  // Wpt[k][c] = W_proj[c*DD+k]
        g_Wp4[idx] = make_float4(wr[0], wr[1], wr[2], wr[3]);
    }
}

// ---------------- persistent fused GRU decode ----------------
// One CTA per SM owns 14 batch rows for the ENTIRE sequence (rows independent).
// smem: hA[512][20] + hB[512][20] (transposed h ping-pong, rows 14..19 = pad) + lg[16][128].
__global__ __launch_bounds__(NT) void gru_kernel(
    const float* __restrict__ feat,
    const float* __restrict__ b_hh,
    const float* __restrict__ b_proj,
    float* __restrict__ out_tok)     // d_out + B*C*T (float tokens), or null
{
    extern __shared__ float sm[];
    float* hA = sm;                   // [k][HSTR]
    float* hB = sm + DD * HSTR;
    float* lg = sm + 2 * DD * HSTR;   // [16][128] (rows 14,15 scratch)
    __shared__ int tok_s[ROWS];

    const int tid = threadIdx.x;
    const int rb  = blockIdx.x * ROWS;

    // ---- load feat tile transposed into hA (h0 = feat); fake rows (>=BB) -> 0 ----
    #pragma unroll
    for (int i = 0; i < 4; i++) {
        int idx = tid + i * NT;       // need 14*128 = 1792 float4
        if (idx < ROWS * 128) {
            int b  = idx >> 7;
            int kq = idx & 127;
            float4 v = make_float4(0.f, 0.f, 0.f, 0.f);
            if (rb + b < BB)
                v = *(const float4*)(feat + (size_t)(rb + b) * DD + kq * 4);
            int base = (kq * 4) * HSTR + b;
            hA[base]            = v.x;
            hA[base + HSTR]     = v.y;
            hA[base + 2 * HSTR] = v.z;
            hA[base + 3 * HSTR] = v.w;
        }
    }
    if (tid < ROWS) tok_s[tid] = CC;  // x0 = 0 -> G row 128 (= b_ih only)
    __syncthreads();

    // per-thread invariants
    const int d = tid;                              // gh: owns gate dim d
    const float bhr = __ldg(&b_hh[d]);
    const float bhz = __ldg(&b_hh[DD + d]);
    const float bhn = __ldg(&b_hh[2 * DD + d]);
    const int   lc   = tid & 127;                   // logits: owns column lc
    const int   lb0  = (tid >> 7) * 4;              // ... for rows lb0..lb0+3 (group 3 partly scratch)
    const float bpc  = __ldg(&b_proj[lc]);

    for (int t = 0; t < TT; t++) {
        float* cur = (t & 1) ? hB : hA;
        float* nxt = (t & 1) ? hA : hB;

        // ---- gh GEMM: acc[j][b] = sum_k Wt[k][j] * h[k][b] ----
        // Weights: float4 k-packs, double-buffered at kq granularity.
        // h rows: REGISTER double-buffered — row k+1 is LDS-loaded BEFORE row k's
        // 21 fma2 issue, so the 29-cycle LDS latency hides behind >21 warp-issues
        // (the R11/R14 profiles showed a ~380-cyc/kq bubble from LDS->FFMA RAW).
        // The one-past-the-end row-512 read lands in the next smem buffer (safe, unused).
        ull ar[PAIRS], az[PAIRS], an[PAIRS];
        #pragma unroll
        for (int p = 0; p < PAIRS; p++) { ar[p] = 0ULL; az[p] = 0ULL; an[p] = 0ULL; }

        float4 wbuf[2][3];
        const float4* wbase = g_W4 + d;
        wbuf[0][0] = __ldg(wbase);
        wbuf[0][1] = __ldg(wbase + DD);
        wbuf[0][2] = __ldg(wbase + 2 * DD);
        const float* hrow = cur;
        // preload h row 0
        ulonglong2 hu0 = *(const ulonglong2*)(hrow);
        ulonglong2 hu1 = *(const ulonglong2*)(hrow + 4);
        ulonglong2 hu2 = *(const ulonglong2*)(hrow + 8);
        ull        hu3 = *(const ull*)(hrow + 12);
        hrow += HSTR;
        #pragma unroll 4
        for (int kq = 0; kq < 128; kq++) {
            const int cb = kq & 1, nb = cb ^ 1;
            if (kq < 127) {                    // prefetch next kq weight block
                const float4* w = wbase + (size_t)(kq + 1) * G3;
                wbuf[nb][0] = __ldg(w);
                wbuf[nb][1] = __ldg(w + DD);
                wbuf[nb][2] = __ldg(w + 2 * DD);
            }
            #pragma unroll
            for (int kk = 0; kk < 4; kk++) {
                // load NEXT h row (k+1) first — consumers are a full kk-body away
                ulonglong2 nu0 = *(const ulonglong2*)(hrow);
                ulonglong2 nu1 = *(const ulonglong2*)(hrow + 4);
                ulonglong2 nu2 = *(const ulonglong2*)(hrow + 8);
                ull        nu3 = *(const ull*)(hrow + 12);
                hrow += HSTR;
                float wr = f4c(wbuf[cb][0], kk);
                float wz = f4c(wbuf[cb][1], kk);
                float wn = f4c(wbuf[cb][2], kk);
                ull wr2 = pack2(wr, wr);
                ull wz2 = pack2(wz, wz);
                ull wn2 = pack2(wn, wn);
                fma2(ar[0], wr2, hu0.x); fma2(az[0], wz2, hu0.x); fma2(an[0], wn2, hu0.x);
                fma2(ar[1], wr2, hu0.y); fma2(az[1], wz2, hu0.y); fma2(an[1], wn2, hu0.y);
                fma2(ar[2], wr2, hu1.x); fma2(az[2], wz2, hu1.x); fma2(an[2], wn2, hu1.x);
                fma2(ar[3], wr2, hu1.y); fma2(az[3], wz2, hu1.y); fma2(an[3], wn2, hu1.y);
                fma2(ar[4], wr2, hu2.x); fma2(az[4], wz2, hu2.x); fma2(an[4], wn2, hu2.x);
                fma2(ar[5], wr2, hu2.y); fma2(az[5], wz2, hu2.y); fma2(an[5], wn2, hu2.y);
                fma2(ar[6], wr2, hu3);   fma2(az[6], wz2, hu3);   fma2(an[6], wn2, hu3);
                hu0 = nu0; hu1 = nu1; hu2 = nu2; hu3 = nu3;
            }
        }

        // ---- gates + h_new (gi gathers batched so ptxas can front-issue them) ----
        #pragma unroll
        for (int p = 0; p < PAIRS; p++) {
            float2 rr = unpack2(ar[p]);
            float2 zz = unpack2(az[p]);
            float2 nn = unpack2(an[p]);
            const float* gi0 = g_G + (size_t)tok_s[2 * p] * G3;
            const float* gi1 = g_G + (size_t)tok_s[2 * p + 1] * G3;
            float gr0 = __ldg(&gi0[d]), gz0 = __ldg(&gi0[DD + d]), gn0 = __ldg(&gi0[2 * DD + d]);
            float gr1 = __ldg(&gi1[d]), gz1 = __ldg(&gi1[DD + d]), gn1 = __ldg(&gi1[2 * DD + d]);
            {
                int b = 2 * p;
                float r = 1.f / (1.f + expf(-(gr0 + rr.x + bhr)));
                float z = 1.f / (1.f + expf(-(gz0 + zz.x + bhz)));
                float n = tanhf(gn0 + r * (nn.x + bhn));
                float ho = cur[d * HSTR + b];
                nxt[d * HSTR + b] = (1.f - z) * n + z * ho;
            }
            {
                int b = 2 * p + 1;
                float r = 1.f / (1.f + expf(-(gr1 + rr.y + bhr)));
                float z = 1.f / (1.f + expf(-(gz1 + zz.y + bhz)));
                float n = tanhf(gn1 + r * (nn.y + bhn));
                float ho = cur[d * HSTR + b];
                nxt[d * HSTR + b] = (1.f - z) * n + z * ho;
            }
        }
        __syncthreads();   // h_new complete

        // ---- logits GEMM: thread = (col lc, rows lb0..lb0+3), register-pipelined LDS ----
        // (group lb0=12: rows 14,15 are uninitialized pad -> garbage into lg scratch rows, never used;
        //  one-past-the-end row-512 read lands in following smem buffer, safe)
        {
            ull a0 = 0ULL, a1 = 0ULL;
            const float4* wp4 = g_Wp4 + lc;
            const float* hr = nxt + lb0;
            ulonglong2 H = *(const ulonglong2*)(hr);   // preload row 0
            hr += HSTR;
            #pragma unroll 4
            for (int kq = 0; kq < 128; kq++) {
                float4 w4 = __ldg(wp4); wp4 += CC;
                #pragma unroll
                for (int kk = 0; kk < 4; kk++) {
                    ulonglong2 Hn = *(const ulonglong2*)(hr);   // next row first
                    hr += HSTR;
                    float w = f4c(w4, kk);
                    ull w2 = pack2(w, w);
                    fma2(a0, w2, H.x);
                    fma2(a1, w2, H.y);
                    H = Hn;
                }
            }
            float2 v0 = unpack2(a0);
            float2 v1 = unpack2(a1);
            lg[(lb0    ) * 128 + lc] = v0.x + bpc;
            lg[(lb0 + 1) * 128 + lc] = v0.y + bpc;
            lg[(lb0 + 2) * 128 + lc] = v1.x + bpc;
            lg[(lb0 + 3) * 128 + lc] = v1.y + bpc;
        }
        __syncthreads();   // logits complete

        // ---- stage logits [B][T][C] coalesced, streaming ----
        if (tid < ROWS * 32) {        // 448 float4 = 14*128
            int b  = tid >> 5;
            int cq = tid & 31;
            if (rb + b < BB) {
                float4 v = *(const float4*)(lg + b * 128 + cq * 4);
                st_cs4(g_stage + ((size_t)(rb + b) * TT + t) * CC + cq * 4, v);
            }
        }

        // ---- parallel argmax (first-max semantics) + token feedback ----
        if (tid < ROWS * 16) {        // 224 threads = 7 full warps
            int row = tid >> 4;
            int l16 = tid & 15;
            const float* lrow = lg + row * 128;
            float best = -3.4e38f;
            int bi = 0;
            #pragma unroll
            for (int j = 0; j < 8; j++) {
                int c = l16 + 16 * j;          // increasing c per thread
                float v = lrow[c];
                if (v > best) { best = v; bi = c; }
            }
            #pragma unroll
            for (int mask = 8; mask >= 1; mask >>= 1) {
                float ob  = __shfl_xor_sync(0xffffffffu, best, mask);
                int   obi = __shfl_xor_sync(0xffffffffu, bi,   mask);
                if (ob > best || (ob == best && obi < bi)) { best = ob; bi = obi; }
            }
            if (l16 == 0) {
                tok_s[row] = bi;               // always 0..127: g_G index stays in-bounds even for fake rows
                if (out_tok && rb + row < BB)
                    out_tok[(size_t)(rb + row) * TT + t] = (float)bi;
            }
        }
        __syncthreads();   // tok_s ready; lg & old cur free for reuse
    }
}

// ---------------- final transpose: stage[B][T][C] -> out[B][C][T] ----------------
__global__ void transpose_kernel(float* __restrict__ out) {
    __shared__ float tile[32][33];
    int b  = blockIdx.z;
    int t0 = blockIdx.x * 32;
    int c0 = blockIdx.y * 32;
    int tx = threadIdx.x, ty = threadIdx.y;   // block (32,8)
    #pragma unroll
    for (int i = 0; i < 4; i++) {
        int t = t0 + ty + i * 8;
        if (t < TT)
            tile[ty + i * 8][tx] = ld_cs(&g_stage[((size_t)b * TT + t) * CC + c0 + tx]);
    }
    __syncthreads();
    #pragma unroll
    for (int i = 0; i < 4; i++) {
        int c = c0 + ty + i * 8;
        int t = t0 + tx;
        if (t < TT)
            st_cs(&out[((size_t)b * CC + c) * TT + t], tile[tx][ty + i * 8]);
    }
}

// ---------------- launch ----------------
extern "C" void kernel_launch(void* const* d_in, const int* in_sizes, int n_in,
                              void* d_out, int out_size) {
    const float* feat   = (const float*)d_in[0];
    const float* W_ih   = (const float*)d_in[1];
    const float* W_hh   = (const float*)d_in[2];
    const float* b_ih   = (const float*)d_in[3];
    const float* b_hh   = (const float*)d_in[4];
    const float* W_proj = (const float*)d_in[5];
    const float* b_proj = (const float*)d_in[6];
    const float* embed  = (const float*)d_in[7];
    float* out = (float*)d_out;

    const int SMEM_BYTES = (2 * DD * HSTR + 16 * CC) * 4;   // 90112
    cudaFuncSetAttribute(gru_kernel, cudaFuncAttributeMaxDynamicSharedMemorySize, SMEM_BYTES);

    // precompute (cheap; replayed each graph iteration)
    precomp_G<<<129, 256>>>(embed, W_ih, b_ih);
    precomp_W4<<<((DD / 4) * G3 + 255) / 256, 256>>>(W_hh);
    precomp_Wp4<<<((DD / 4) * CC + 255) / 256, 256>>>(W_proj);

    const long long expected = (long long)BB * CC * TT + (long long)BB * TT;
    float* out_tok = ((long long)out_size >= expected) ? out + (size_t)BB * CC * TT : nullptr;

    // persistent kernel: whole T loop inside, one CTA per SM
    gru_kernel<<<NCTA, NT, SMEM_BYTES>>>(feat, b_hh, b_proj, out_tok);

    dim3 tb(32, 8);
    dim3 tg((TT + 31) / 32, CC / 32, BB);
    transpose_kernel<<<tg, tb>>>(out);
}